// round 1
// baseline (speedup 1.0000x reference)
#include <cuda_runtime.h>
#include <math.h>

// YOLO-v1 loss: pure HBM-bound streaming reduction.
// predictions, target: [N, S, S, 30] fp32; output: scalar fp32.
//
// Stage 1: each block stages 128 cells (128*30 floats per array) into smem via
//          fully-coalesced float4 loads, computes per-cell loss, tree-reduces,
//          writes one partial per block to a __device__ global.
// Stage 2: one block reduces all partials in double precision -> d_out[0].

#define DPC 30                 // features per cell
#define CELLS_PER_BLOCK 128
#define NTHREADS 128
#define MAX_PARTIALS 65536     // supports up to 8.4M cells

__device__ float g_partials[MAX_PARTIALS];

__device__ __forceinline__ float iou_sq(float x1, float y1, float w1,
                                        float x2, float y2, float w2) {
    // h1 = w1, h2 = w2 per the reference
    float wi = fminf(x1 + w1, x2 + w2) - fmaxf(x1, x2);
    float hi = fminf(y1 + w1, y2 + w2) - fmaxf(y1, y2);
    float inter = wi * hi;
    float uni = w1 * w1 + w2 * w2 - inter;
    return (wi > 0.0f && hi > 0.0f) ? inter / uni : 0.0f;
}

__global__ void __launch_bounds__(NTHREADS)
yolo_loss_kernel(const float* __restrict__ pred,
                 const float* __restrict__ tgt,
                 int num_cells) {
    __shared__ float sp[CELLS_PER_BLOCK * DPC];   // 15360 B
    __shared__ float st[CELLS_PER_BLOCK * DPC];   // 15360 B

    const int tid = threadIdx.x;
    const long long cell0 = (long long)blockIdx.x * CELLS_PER_BLOCK;
    const long long base = cell0 * DPC;

    // ---- coalesced float4 staging ----
    int cells_here = num_cells - (int)cell0;
    if (cells_here > CELLS_PER_BLOCK) cells_here = CELLS_PER_BLOCK;
    const int nfloats = cells_here * DPC;           // multiple of 2 (30 per cell)
    // base byte offset is cell0*120, 8B aligned always; 16B aligned when cell0*120 % 16 == 0
    // cell0 is a multiple of 128 -> base*4 = cell0*120 bytes, 128*120 = 15360 % 16 == 0. OK.
    const float4* p4 = reinterpret_cast<const float4*>(pred + base);
    const float4* t4 = reinterpret_cast<const float4*>(tgt + base);
    float4* sp4 = reinterpret_cast<float4*>(sp);
    float4* st4 = reinterpret_cast<float4*>(st);
    const int n4 = nfloats >> 2;                    // 960 for full blocks (nfloats%4==0: 30*cells even? 30*128=3840 ok)
    for (int i = tid; i < n4; i += NTHREADS) {
        sp4[i] = p4[i];
        st4[i] = t4[i];
    }
    // tail floats (only possible on a ragged last block)
    for (int i = (n4 << 2) + tid; i < nfloats; i += NTHREADS) {
        sp[i] = pred[base + i];
        st[i] = tgt[base + i];
    }
    __syncthreads();

    // ---- per-cell loss ----
    float loss = 0.0f;
    if (tid < cells_here) {
        const float* p = sp + tid * DPC;
        const float* t = st + tid * DPC;

        const float t0 = t[0], t1 = t[1], t2 = t[2], t3 = t[3];
        const float obj = (t[4] == 1.0f) ? 1.0f : 0.0f;

        const float p0 = p[0], p1 = p[1], p2 = p[2], p3 = p[3], p4v = p[4];
        const float p5 = p[5], p6 = p[6], p7 = p[7], p8 = p[8], p9 = p[9];

        const float i1 = iou_sq(p0, p1, p2, t0, t1, t2);
        const float i2 = iou_sq(p5, p6, p7, t0, t1, t2);
        const bool c1 = i1 > i2;

        const float rx = c1 ? p0 : p5;
        const float ry = c1 ? p1 : p6;
        const float rw = c1 ? p2 : p7;
        const float rh = c1 ? p3 : p8;
        const float rc = c1 ? p4v : p9;
        const float oc = c1 ? p9 : p4v;

        // xy loss
        const float dx = rx - t0, dy = ry - t1;
        loss += 5.0f * obj * (dx * dx + dy * dy);
        // wh loss
        const float sw = sqrtf(fabsf(rw)) - sqrtf(t2);
        const float sh = sqrtf(fabsf(rh)) - sqrtf(t3);
        loss += 5.0f * obj * (sw * sw + sh * sh);
        // object loss
        const float dc = 1.0f - rc;
        loss += obj * dc * dc;
        // no-object loss
        loss += 0.5f * obj * oc * oc;
        loss += 0.5f * (1.0f - obj) * (p4v * p4v + p9 * p9);
        // class loss
        float cls = 0.0f;
        #pragma unroll
        for (int k = 10; k < 30; k++) {
            const float d = p[k] - t[k];
            cls += d * d;
        }
        loss += obj * cls;
    }

    // ---- block tree reduction (deterministic) ----
    #pragma unroll
    for (int off = 16; off > 0; off >>= 1)
        loss += __shfl_down_sync(0xFFFFFFFFu, loss, off);

    __shared__ float warp_sums[NTHREADS / 32];
    if ((tid & 31) == 0) warp_sums[tid >> 5] = loss;
    __syncthreads();
    if (tid == 0) {
        float s = 0.0f;
        #pragma unroll
        for (int w = 0; w < NTHREADS / 32; w++) s += warp_sums[w];
        g_partials[blockIdx.x] = s;
    }
}

__global__ void __launch_bounds__(256)
yolo_reduce_kernel(float* __restrict__ out, int nblocks) {
    __shared__ double sd[256];
    double acc = 0.0;
    for (int i = threadIdx.x; i < nblocks; i += 256)
        acc += (double)g_partials[i];
    sd[threadIdx.x] = acc;
    __syncthreads();
    #pragma unroll
    for (int s = 128; s > 0; s >>= 1) {
        if (threadIdx.x < s) sd[threadIdx.x] += sd[threadIdx.x + s];
        __syncthreads();
    }
    if (threadIdx.x == 0) out[0] = (float)sd[0];
}

extern "C" void kernel_launch(void* const* d_in, const int* in_sizes, int n_in,
                              void* d_out, int out_size) {
    const float* pred = (const float*)d_in[0];
    const float* tgt  = (const float*)d_in[1];
    float* out = (float*)d_out;

    const int num_cells = in_sizes[0] / DPC;                 // 1,605,632
    const int nblocks = (num_cells + CELLS_PER_BLOCK - 1) / CELLS_PER_BLOCK;  // 12,544

    yolo_loss_kernel<<<nblocks, NTHREADS>>>(pred, tgt, num_cells);
    yolo_reduce_kernel<<<1, 256>>>(out, nblocks);
}